// round 14
// baseline (speedup 1.0000x reference)
#include <cuda_runtime.h>
#include <cuda_bf16.h>
#include <cuda_fp16.h>
#include <cstdint>

#define NN 50000
#define EE 400000
#define EPS_SKIP_F 1.000001f

// ---------------- scratch ----------------
__device__ __half   g_xm[2][NN * 128];   // per-branch transformed features (fp16)
__device__ float    g_ssrc[2][NN * 4];
__device__ float    g_sdst[2][NN * 4];
__device__ int      g_deg[2 * NN];
__device__ int      g_off[2 * NN];
__device__ int      g_cur[2 * NN];
__device__ int      g_psrc[2 * EE];      // target-sorted source indices
__device__ int      g_total;             // global segment cursor
__device__ uint32_t g_Wtp[3][2][128 * 64];  // W^T split: [branch][hi/lo][n][kpair] bf16x2

// ---------------- helpers ----------------
__device__ __forceinline__ void split_pack(float v0, float v1, uint32_t& hi, uint32_t& lo) {
    __nv_bfloat16 h0 = __float2bfloat16_rn(v0);
    __nv_bfloat16 h1 = __float2bfloat16_rn(v1);
    float r0 = v0 - __bfloat162float(h0);
    float r1 = v1 - __bfloat162float(h1);
    __nv_bfloat162 hp; hp.x = h0; hp.y = h1;
    __nv_bfloat162 lp; lp.x = __float2bfloat16_rn(r0); lp.y = __float2bfloat16_rn(r1);
    hi = *(uint32_t*)&hp;
    lo = *(uint32_t*)&lp;
}

__device__ __forceinline__ void mma_bf16(float* d,
                                         uint32_t a0, uint32_t a1, uint32_t a2, uint32_t a3,
                                         uint32_t b0, uint32_t b1) {
    asm volatile(
        "mma.sync.aligned.m16n8k16.row.col.f32.bf16.bf16.f32 "
        "{%0,%1,%2,%3}, {%4,%5,%6,%7}, {%8,%9}, {%0,%1,%2,%3};"
        : "+f"(d[0]), "+f"(d[1]), "+f"(d[2]), "+f"(d[3])
        : "r"(a0), "r"(a1), "r"(a2), "r"(a3), "r"(b0), "r"(b1));
}

__device__ __forceinline__ float lrelu_exp(float a) {
    a = (a > 0.f) ? a : 0.01f * a;
    return __expf(a);
}

// ---------------- zero (side stream): deg + cursor ----------------
__global__ void zero_kernel() {
    int i = blockIdx.x * blockDim.x + threadIdx.x;
    if (i == 0) g_total = 0;
    if (i < 2 * NN) g_deg[i] = 0;
}

// ---------------- prep: W split/transpose only ----------------
__global__ void prep_b_kernel(const float* __restrict__ Wl,
                              const float* __restrict__ Wu,
                              const float* __restrict__ Ws) {
    int i = blockIdx.x * blockDim.x + threadIdx.x;
    if (i >= 3 * 8192) return;
    const int b = i / 8192;
    const int r = i & 8191;
    const int n = r >> 6, kp = r & 63;
    const float* __restrict__ W = (b == 0) ? Wl : ((b == 1) ? Wu : Ws);
    const float v0 = W[(2 * kp) * 128 + n];
    const float v1 = W[(2 * kp + 1) * 128 + n];
    uint32_t hi, lo;
    split_pack(v0, v1, hi, lo);
    g_Wtp[b][0][n * 64 + kp] = hi;
    g_Wtp[b][1][n * 64 + kp] = lo;
}

// ---------------- branch-per-CTA bf16x3 GEMM + logit epilogue ----------------
// grid = (391, 2, 3): x-tile 128 rows, N-half 64 cols, branch. occ 2 target.
#define PADP 68
#define ASZ  (128 * PADP)
#define BSZ  (64 * PADP)
#define GEMM_SMEM ((2 * ASZ + 2 * BSZ) * 4)   // Ah, Al, Bh, Bl = 104.5 KB

__global__ __launch_bounds__(256, 2) void gemm_mma_kernel(
    const float* __restrict__ x, float* __restrict__ out_skip,
    const float* __restrict__ a_sl, const float* __restrict__ a_dl,
    const float* __restrict__ a_su, const float* __restrict__ a_du)
{
    extern __shared__ uint32_t smem[];
    uint32_t* Ah = smem;
    uint32_t* Al = smem + ASZ;
    uint32_t* Bh = smem + 2 * ASZ;
    uint32_t* Bl = smem + 2 * ASZ + BSZ;

    const int nh = blockIdx.y;          // N-half: cols [nh*64, nh*64+64)
    const int bz = blockIdx.z;          // branch 0=low, 1=up, 2=skip
    const int bm0 = blockIdx.x * 128;

    const int t = threadIdx.x;
    const int wid = t >> 5, lane = t & 31;
    const int lg = lane >> 2;
    const int lt = lane & 3;

    // ---- load + split A tile ----
#pragma unroll
    for (int i = t; i < 4096; i += 256) {
        const int row = i >> 5;
        const int c4 = i & 31;
        const int m = bm0 + row;
        float4 v = make_float4(0.f, 0.f, 0.f, 0.f);
        if (m < NN) v = *(const float4*)&x[m * 128 + c4 * 4];
        uint32_t h0, l0, h1, l1;
        split_pack(v.x, v.y, h0, l0);
        split_pack(v.z, v.w, h1, l1);
        const int base = row * PADP + 2 * c4;
        Ah[base] = h0; Ah[base + 1] = h1;
        Al[base] = l0; Al[base + 1] = l1;
    }
    // ---- load this branch's B half-tile ----
#pragma unroll
    for (int i = t; i < 1024; i += 256) {
        const int n = i >> 4;           // 0..63 local
        const int p4 = i & 15;
        const int gn = nh * 64 + n;
        uint4 vh = *(const uint4*)&g_Wtp[bz][0][gn * 64 + p4 * 4];
        uint4 vl = *(const uint4*)&g_Wtp[bz][1][gn * 64 + p4 * 4];
        *(uint4*)&Bh[n * PADP + p4 * 4] = vh;
        *(uint4*)&Bl[n * PADP + p4 * 4] = vl;
    }
    __syncthreads();

    // warp tile: 32 rows x 32 cols; 4x2 warps cover 128x64
    const int wm = (wid & 3) * 32;
    const int wn = (wid >> 2) * 32;

    float acc[2][4][4];
#pragma unroll
    for (int mt = 0; mt < 2; mt++)
#pragma unroll
        for (int nt = 0; nt < 4; nt++)
#pragma unroll
            for (int c = 0; c < 4; c++) acc[mt][nt][c] = 0.f;

#pragma unroll
    for (int ks = 0; ks < 8; ks++) {
        const int kp = ks * 8;
        uint32_t ah[2][4], al[2][4];
#pragma unroll
        for (int mt = 0; mt < 2; mt++) {
            const int rb = wm + mt * 16 + lg;
            const int i0 = rb * PADP + kp + lt;
            const int i1 = (rb + 8) * PADP + kp + lt;
            ah[mt][0] = Ah[i0];     al[mt][0] = Al[i0];
            ah[mt][1] = Ah[i1];     al[mt][1] = Al[i1];
            ah[mt][2] = Ah[i0 + 4]; al[mt][2] = Al[i0 + 4];
            ah[mt][3] = Ah[i1 + 4]; al[mt][3] = Al[i1 + 4];
        }
        uint32_t bh[4][2], bl[4][2];
#pragma unroll
        for (int nt = 0; nt < 4; nt++) {
            const int n = wn + nt * 8 + lg;
            const int i0 = n * PADP + kp + lt;
            bh[nt][0] = Bh[i0];     bl[nt][0] = Bl[i0];
            bh[nt][1] = Bh[i0 + 4]; bl[nt][1] = Bl[i0 + 4];
        }
#pragma unroll
        for (int mt = 0; mt < 2; mt++)
#pragma unroll
            for (int nt = 0; nt < 4; nt++) {
                mma_bf16(acc[mt][nt], ah[mt][0], ah[mt][1], ah[mt][2], ah[mt][3],
                         bl[nt][0], bl[nt][1]);
                mma_bf16(acc[mt][nt], al[mt][0], al[mt][1], al[mt][2], al[mt][3],
                         bh[nt][0], bh[nt][1]);
                mma_bf16(acc[mt][nt], ah[mt][0], ah[mt][1], ah[mt][2], ah[mt][3],
                         bh[nt][0], bh[nt][1]);
            }
    }

    // ---- epilogue ----
    if (bz < 2) {
        __half* __restrict__ out = g_xm[bz];
#pragma unroll
        for (int mt = 0; mt < 2; mt++) {
            const int m0 = bm0 + wm + mt * 16 + lg;
            const int m1 = m0 + 8;
#pragma unroll
            for (int nt = 0; nt < 4; nt++) {
                const int col = nh * 64 + wn + nt * 8 + 2 * lt;
                if (m0 < NN) {
                    __half2 v = __floats2half2_rn(acc[mt][nt][0], acc[mt][nt][1]);
                    *(__half2*)&out[m0 * 128 + col] = v;
                }
                if (m1 < NN) {
                    __half2 v = __floats2half2_rn(acc[mt][nt][2], acc[mt][nt][3]);
                    *(__half2*)&out[m1 * 128 + col] = v;
                }
            }
        }
        // fused logit epilogue: this warp owns head h
        const int h = nh * 2 + (wn >> 5);
        const float* __restrict__ asrc = (bz == 0) ? a_sl : a_su;
        const float* __restrict__ adst = (bz == 0) ? a_dl : a_du;
        float ssum[4] = {0.f, 0.f, 0.f, 0.f};
        float dsum[4] = {0.f, 0.f, 0.f, 0.f};
#pragma unroll
        for (int nt = 0; nt < 4; nt++) {
            const int ai = h * 32 + nt * 8 + 2 * lt;
            const float s0 = asrc[ai], s1 = asrc[ai + 1];
            const float d0 = adst[ai], d1 = adst[ai + 1];
#pragma unroll
            for (int mt = 0; mt < 2; mt++) {
                ssum[mt * 2 + 0] += acc[mt][nt][0] * s0 + acc[mt][nt][1] * s1;
                ssum[mt * 2 + 1] += acc[mt][nt][2] * s0 + acc[mt][nt][3] * s1;
                dsum[mt * 2 + 0] += acc[mt][nt][0] * d0 + acc[mt][nt][1] * d1;
                dsum[mt * 2 + 1] += acc[mt][nt][2] * d0 + acc[mt][nt][3] * d1;
            }
        }
#pragma unroll
        for (int d = 1; d <= 2; d <<= 1)
#pragma unroll
            for (int rr = 0; rr < 4; rr++) {
                ssum[rr] += __shfl_xor_sync(0xFFFFFFFF, ssum[rr], d);
                dsum[rr] += __shfl_xor_sync(0xFFFFFFFF, dsum[rr], d);
            }
        if (lt == 0) {
#pragma unroll
            for (int rr = 0; rr < 4; rr++) {
                const int row = bm0 + wm + ((rr & 1) ? 8 : 0) + ((rr >> 1) ? 16 : 0) + lg;
                if (row < NN) {
                    g_ssrc[bz][row * 4 + h] = ssum[rr];
                    g_sdst[bz][row * 4 + h] = dsum[rr];
                }
            }
        }
    } else {
#pragma unroll
        for (int mt = 0; mt < 2; mt++) {
            const int m0 = bm0 + wm + mt * 16 + lg;
            const int m1 = m0 + 8;
#pragma unroll
            for (int nt = 0; nt < 4; nt++) {
                const int col = nh * 64 + wn + nt * 8 + 2 * lt;
                if (m0 < NN) {
                    float2 v = make_float2(acc[mt][nt][0] * EPS_SKIP_F,
                                           acc[mt][nt][1] * EPS_SKIP_F);
                    *(float2*)&out_skip[m0 * 128 + col] = v;
                }
                if (m1 < NN) {
                    float2 v = make_float2(acc[mt][nt][2] * EPS_SKIP_F,
                                           acc[mt][nt][3] * EPS_SKIP_F);
                    *(float2*)&out_skip[m1 * 128 + col] = v;
                }
            }
        }
    }
}

// ---------------- deg: pure in-degree histogram ----------------
__global__ void deg_kernel(const int* __restrict__ t0, const int* __restrict__ t1)
{
    int idx = blockIdx.x * blockDim.x + threadIdx.x;
    if (idx >= 2 * EE) return;
    const int branch = (idx >= EE) ? 1 : 0;
    const int e = idx - branch * EE;
    const int tgt = (branch ? t1 : t0)[e];
    atomicAdd(&g_deg[branch * NN + tgt], 1);
}

// ---------------- alloc: warp-aggregated order-free CSR segment allocation ----------------
__global__ void alloc_kernel() {
    const int i = blockIdx.x * blockDim.x + threadIdx.x;
    if (i >= 2 * NN) return;
    const int lane = threadIdx.x & 31;
    const int deg = g_deg[i];
    int incl = deg;
#pragma unroll
    for (int d = 1; d < 32; d <<= 1) {
        int v = __shfl_up_sync(0xFFFFFFFF, incl, d);
        if (lane >= d) incl += v;
    }
    const int excl = incl - deg;
    int base = 0;
    if (lane == 31) base = atomicAdd(&g_total, incl);
    base = __shfl_sync(0xFFFFFFFF, base, 31);
    g_off[i] = base + excl;
    g_cur[i] = base + excl;
}

// ---------------- scatter: src indices into target-sorted order ----------------
__global__ void scatter_kernel(const int* __restrict__ t0, const int* __restrict__ s0,
                               const int* __restrict__ t1, const int* __restrict__ s1)
{
    int idx = blockIdx.x * blockDim.x + threadIdx.x;
    if (idx >= 2 * EE) return;
    const int branch = (idx >= EE) ? 1 : 0;
    const int e = idx - branch * EE;
    const int tgt = (branch ? t1 : t0)[e];
    const int src = (branch ? s1 : s0)[e];
    int pos = atomicAdd(&g_cur[branch * NN + tgt], 1);
    g_psrc[pos] = src;
}

// ---------------- agg: warp per node; fp16 gathers; inline softmax; single write ----------------
__global__ __launch_bounds__(256) void agg_kernel(float* __restrict__ out)
{
    const int gw = (blockIdx.x * blockDim.x + threadIdx.x) >> 5;
    if (gw >= NN) return;
    const int n = gw;
    const int lane = threadIdx.x & 31;
    const int h = lane >> 3;

    float4 acc = make_float4(0.f, 0.f, 0.f, 0.f);
#pragma unroll
    for (int b = 0; b < 2; b++) {
        const int base_i = b * NN + n;
        const int off = g_off[base_i];
        const int deg = g_deg[base_i];
        const float sdh = g_sdst[b][n * 4 + h];
        const __half* __restrict__ xm = g_xm[b];
        const float* __restrict__ ssrc = g_ssrc[b];

        float4 accb = make_float4(0.f, 0.f, 0.f, 0.f);
        float sumw = 0.f;
        for (int bs = 0; bs < deg; bs += 32) {
            const int cnt = min(deg - bs, 32);
            const int my = (lane < cnt) ? g_psrc[off + bs + lane] : 0;
#pragma unroll 4
            for (int j = 0; j < cnt; j++) {
                const int s = __shfl_sync(0xFFFFFFFF, my, j);
                const float ssh = __ldg(&ssrc[s * 4 + h]);
                const __half2* hp = (const __half2*)&xm[s * 128 + lane * 4];
                const float2 v01 = __half22float2(hp[0]);
                const float2 v23 = __half22float2(hp[1]);
                const float w = lrelu_exp(ssh + sdh);
                sumw += w;
                accb.x += w * v01.x;
                accb.y += w * v01.y;
                accb.z += w * v23.x;
                accb.w += w * v23.y;
            }
        }
        const float inv = __frcp_rn(sumw + 1e-16f);
        acc.x += accb.x * inv;
        acc.y += accb.y * inv;
        acc.z += accb.z * inv;
        acc.w += accb.w * inv;
    }
    float4* po = (float4*)&out[n * 128 + lane * 4];
    float4 o = *po;   // skip*EPS already written by gemm
    o.x = fmaxf(o.x + acc.x, 0.f);
    o.y = fmaxf(o.y + acc.y, 0.f);
    o.z = fmaxf(o.z + acc.z, 0.f);
    o.w = fmaxf(o.w + acc.w, 0.f);
    *po = o;
}

// ---------------- launch ----------------
extern "C" void kernel_launch(void* const* d_in, const int* in_sizes, int n_in,
                              void* d_out, int out_size)
{
    const float* x      = (const float*)d_in[0];
    const float* W_low  = (const float*)d_in[1];
    const float* a_sl   = (const float*)d_in[2];
    const float* a_dl   = (const float*)d_in[3];
    const float* W_up   = (const float*)d_in[4];
    const float* a_su   = (const float*)d_in[5];
    const float* a_du   = (const float*)d_in[6];
    const float* W_skip = (const float*)d_in[7];
    const int* lower_tgt = (const int*)d_in[8];
    const int* lower_src = (const int*)d_in[9];
    const int* upper_tgt = (const int*)d_in[10];
    const int* upper_src = (const int*)d_in[11];
    float* out = (float*)d_out;

    static cudaStream_t s2 = nullptr;
    static cudaEvent_t e_fork = nullptr, e_join = nullptr;
    if (!s2) {
        cudaFuncSetAttribute(gemm_mma_kernel,
                             cudaFuncAttributeMaxDynamicSharedMemorySize, GEMM_SMEM);
        cudaStreamCreateWithFlags(&s2, cudaStreamNonBlocking);
        cudaEventCreateWithFlags(&e_fork, cudaEventDisableTiming);
        cudaEventCreateWithFlags(&e_join, cudaEventDisableTiming);
    }

    // fork: CSR chain on side stream, GEMM chain on main stream
    cudaEventRecord(e_fork, 0);
    cudaStreamWaitEvent(s2, e_fork, 0);

    // side stream: zero -> deg -> alloc -> scatter
    zero_kernel<<<(2 * NN + 255) / 256, 256, 0, s2>>>();
    deg_kernel<<<(2 * EE + 255) / 256, 256, 0, s2>>>(lower_tgt, upper_tgt);
    alloc_kernel<<<(2 * NN + 255) / 256, 256, 0, s2>>>();
    scatter_kernel<<<(2 * EE + 255) / 256, 256, 0, s2>>>(lower_tgt, lower_src,
                                                         upper_tgt, upper_src);
    cudaEventRecord(e_join, s2);

    // main stream: prep -> gemm (branch-per-CTA, occ 2)
    prep_b_kernel<<<(3 * 8192 + 255) / 256, 256>>>(W_low, W_up, W_skip);
    dim3 ggrid((NN + 127) / 128, 2, 3);
    gemm_mma_kernel<<<ggrid, 256, GEMM_SMEM>>>(x, out, a_sl, a_dl, a_su, a_du);

    // join: agg needs gemm (main) + scatter (side)
    cudaStreamWaitEvent(0, e_join, 0);
    {
        long long threads = (long long)NN * 32;
        int blocks = (int)((threads + 255) / 256);
        agg_kernel<<<blocks, 256>>>(out);
    }
}

// round 15
// speedup vs baseline: 1.0630x; 1.0630x over previous
#include <cuda_runtime.h>
#include <cuda_bf16.h>
#include <cuda_fp16.h>
#include <cstdint>

#define NN 50000
#define EE 400000
#define EPS_SKIP_F 1.000001f

// ---------------- scratch ----------------
__device__ __half   g_xm[2][NN * 128];   // per-branch transformed features (fp16)
__device__ float    g_ssrc[2][NN * 4];
__device__ float    g_sdst[2][NN * 4];
__device__ int      g_deg[2 * NN];
__device__ int      g_off[2 * NN];
__device__ int      g_cur[2 * NN];
__device__ int      g_psrc[2 * EE];      // target-sorted source indices
__device__ int      g_total;             // global segment cursor
__device__ uint32_t g_Wtp[3][2][128 * 64];  // W^T split: [branch][hi/lo][n][kpair] bf16x2

// ---------------- helpers ----------------
__device__ __forceinline__ void split_pack(float v0, float v1, uint32_t& hi, uint32_t& lo) {
    __nv_bfloat16 h0 = __float2bfloat16_rn(v0);
    __nv_bfloat16 h1 = __float2bfloat16_rn(v1);
    float r0 = v0 - __bfloat162float(h0);
    float r1 = v1 - __bfloat162float(h1);
    __nv_bfloat162 hp; hp.x = h0; hp.y = h1;
    __nv_bfloat162 lp; lp.x = __float2bfloat16_rn(r0); lp.y = __float2bfloat16_rn(r1);
    hi = *(uint32_t*)&hp;
    lo = *(uint32_t*)&lp;
}

__device__ __forceinline__ void mma_bf16(float* d,
                                         uint32_t a0, uint32_t a1, uint32_t a2, uint32_t a3,
                                         uint32_t b0, uint32_t b1) {
    asm volatile(
        "mma.sync.aligned.m16n8k16.row.col.f32.bf16.bf16.f32 "
        "{%0,%1,%2,%3}, {%4,%5,%6,%7}, {%8,%9}, {%0,%1,%2,%3};"
        : "+f"(d[0]), "+f"(d[1]), "+f"(d[2]), "+f"(d[3])
        : "r"(a0), "r"(a1), "r"(a2), "r"(a3), "r"(b0), "r"(b1));
}

__device__ __forceinline__ float lrelu_exp(float a) {
    a = (a > 0.f) ? a : 0.01f * a;
    return __expf(a);
}

// ---------------- zero (side stream): deg + cursor ----------------
__global__ void zero_kernel() {
    int i = blockIdx.x * blockDim.x + threadIdx.x;
    if (i == 0) g_total = 0;
    if (i < 2 * NN) g_deg[i] = 0;
}

// ---------------- prep: W split/transpose only ----------------
__global__ void prep_b_kernel(const float* __restrict__ Wl,
                              const float* __restrict__ Wu,
                              const float* __restrict__ Ws) {
    int i = blockIdx.x * blockDim.x + threadIdx.x;
    if (i >= 3 * 8192) return;
    const int b = i / 8192;
    const int r = i & 8191;
    const int n = r >> 6, kp = r & 63;
    const float* __restrict__ W = (b == 0) ? Wl : ((b == 1) ? Wu : Ws);
    const float v0 = W[(2 * kp) * 128 + n];
    const float v1 = W[(2 * kp + 1) * 128 + n];
    uint32_t hi, lo;
    split_pack(v0, v1, hi, lo);
    g_Wtp[b][0][n * 64 + kp] = hi;
    g_Wtp[b][1][n * 64 + kp] = lo;
}

// ---------------- fused 3-branch GEMM: N-quarter tiles, K-chunked, occ>=2 ----------------
// grid = (391, 4): x-tile 128 rows, N-quarter 32 cols (= one head). All 3 branches.
// K processed in 2 chunks of 64 (32 kpairs), A/B buffers reused.
#define PADC 36                          // 36 % 32 == 4 -> conflict-free frag loads
#define ACSZ (128 * PADC)                // 4608 words per A hi/lo buffer
#define BCSZ (32 * PADC)                 // 1152 words per B (branch,hi/lo) buffer
#define GEMM_SMEM ((2 * ACSZ + 6 * BCSZ) * 4)   // 64,512 B -> occ 3 by smem

__global__ __launch_bounds__(256, 2) void gemm_mma_kernel(
    const float* __restrict__ x, float* __restrict__ out_skip,
    const float* __restrict__ a_sl, const float* __restrict__ a_dl,
    const float* __restrict__ a_su, const float* __restrict__ a_du)
{
    extern __shared__ uint32_t smem[];
    uint32_t* Ah = smem;
    uint32_t* Al = smem + ACSZ;
    uint32_t* Bbase = smem + 2 * ACSZ;   // [(b*2+hl)][BCSZ]

    const int nq = blockIdx.y;           // N-quarter: cols [nq*32, nq*32+32) = head nq
    const int bm0 = blockIdx.x * 128;

    const int t = threadIdx.x;
    const int wid = t >> 5, lane = t & 31;
    const int lg = lane >> 2;            // 0..7
    const int lt = lane & 3;             // 0..3
    const int wm = wid * 16;             // warp rows [wm, wm+16)

    float acc[3][4][4];
#pragma unroll
    for (int b = 0; b < 3; b++)
#pragma unroll
        for (int nt = 0; nt < 4; nt++)
#pragma unroll
            for (int c = 0; c < 4; c++) acc[b][nt][c] = 0.f;

#pragma unroll
    for (int ch = 0; ch < 2; ch++) {
        if (ch) __syncthreads();         // protect previous chunk's reads

        // ---- load + split A chunk: 128 rows x 32 kpairs ----
#pragma unroll
        for (int i = t; i < 2048; i += 256) {
            const int row = i >> 4;
            const int c4 = i & 15;       // float4 index within chunk (16 per row)
            const int m = bm0 + row;
            float4 v = make_float4(0.f, 0.f, 0.f, 0.f);
            if (m < NN) v = *(const float4*)&x[m * 128 + (ch * 16 + c4) * 4];
            uint32_t h0, l0, h1, l1;
            split_pack(v.x, v.y, h0, l0);
            split_pack(v.z, v.w, h1, l1);
            const int base = row * PADC + 2 * c4;
            Ah[base] = h0; Ah[base + 1] = h1;
            Al[base] = l0; Al[base + 1] = l1;
        }
        // ---- load B chunk for all 3 branches (hi+lo) ----
#pragma unroll
        for (int i = t; i < 3 * 256; i += 256) {
            const int b = i >> 8;
            const int r = i & 255;
            const int n = r >> 3;        // 0..31 local row
            const int p4 = r & 7;        // uint4 over 32 kpairs
            const int gn = nq * 32 + n;
            uint4 vh = *(const uint4*)&g_Wtp[b][0][gn * 64 + ch * 32 + p4 * 4];
            uint4 vl = *(const uint4*)&g_Wtp[b][1][gn * 64 + ch * 32 + p4 * 4];
            uint32_t* Bh = Bbase + (b * 2 + 0) * BCSZ;
            uint32_t* Bl = Bbase + (b * 2 + 1) * BCSZ;
            *(uint4*)&Bh[n * PADC + p4 * 4] = vh;
            *(uint4*)&Bl[n * PADC + p4 * 4] = vl;
        }
        __syncthreads();

        // ---- compute 4 k16-steps over this chunk ----
#pragma unroll
        for (int ks = 0; ks < 4; ks++) {
            const int kp = ks * 8;
            const int rb = wm + lg;
            const int i0 = rb * PADC + kp + lt;
            const int i1 = (rb + 8) * PADC + kp + lt;
            uint32_t ah[4], al[4];
            ah[0] = Ah[i0];     al[0] = Al[i0];
            ah[1] = Ah[i1];     al[1] = Al[i1];
            ah[2] = Ah[i0 + 4]; al[2] = Al[i0 + 4];
            ah[3] = Ah[i1 + 4]; al[3] = Al[i1 + 4];
#pragma unroll
            for (int b = 0; b < 3; b++) {
                const uint32_t* Bh = Bbase + (b * 2 + 0) * BCSZ;
                const uint32_t* Bl = Bbase + (b * 2 + 1) * BCSZ;
#pragma unroll
                for (int nt = 0; nt < 4; nt++) {
                    const int n = nt * 8 + lg;
                    const int bi = n * PADC + kp + lt;
                    const uint32_t bh0 = Bh[bi], bh1 = Bh[bi + 4];
                    const uint32_t bl0 = Bl[bi], bl1 = Bl[bi + 4];
                    mma_bf16(acc[b][nt], ah[0], ah[1], ah[2], ah[3], bl0, bl1);
                    mma_bf16(acc[b][nt], al[0], al[1], al[2], al[3], bh0, bh1);
                    mma_bf16(acc[b][nt], ah[0], ah[1], ah[2], ah[3], bh0, bh1);
                }
            }
        }
    }

    // ---- epilogue: rows m0 = bm0+wm+lg, m1 = m0+8; cols nq*32 + nt*8 + 2lt ----
    const int m0 = bm0 + wm + lg;
    const int m1 = m0 + 8;
#pragma unroll
    for (int b = 0; b < 2; b++) {
        __half* __restrict__ out = g_xm[b];
#pragma unroll
        for (int nt = 0; nt < 4; nt++) {
            const int col = nq * 32 + nt * 8 + 2 * lt;
            if (m0 < NN) {
                __half2 v = __floats2half2_rn(acc[b][nt][0], acc[b][nt][1]);
                *(__half2*)&out[m0 * 128 + col] = v;
            }
            if (m1 < NN) {
                __half2 v = __floats2half2_rn(acc[b][nt][2], acc[b][nt][3]);
                *(__half2*)&out[m1 * 128 + col] = v;
            }
        }
    }
#pragma unroll
    for (int nt = 0; nt < 4; nt++) {
        const int col = nq * 32 + nt * 8 + 2 * lt;
        if (m0 < NN) {
            float2 v = make_float2(acc[2][nt][0] * EPS_SKIP_F, acc[2][nt][1] * EPS_SKIP_F);
            *(float2*)&out_skip[m0 * 128 + col] = v;
        }
        if (m1 < NN) {
            float2 v = make_float2(acc[2][nt][2] * EPS_SKIP_F, acc[2][nt][3] * EPS_SKIP_F);
            *(float2*)&out_skip[m1 * 128 + col] = v;
        }
    }

    // ---- fused logit epilogue: this warp owns head nq for its 16 rows ----
    const int h = nq;
#pragma unroll
    for (int b = 0; b < 2; b++) {
        const float* __restrict__ asrc = (b == 0) ? a_sl : a_su;
        const float* __restrict__ adst = (b == 0) ? a_dl : a_du;
        float ssum[2] = {0.f, 0.f};
        float dsum[2] = {0.f, 0.f};
#pragma unroll
        for (int nt = 0; nt < 4; nt++) {
            const int ai = h * 32 + nt * 8 + 2 * lt;
            const float s0 = asrc[ai], s1 = asrc[ai + 1];
            const float d0 = adst[ai], d1 = adst[ai + 1];
            ssum[0] += acc[b][nt][0] * s0 + acc[b][nt][1] * s1;
            ssum[1] += acc[b][nt][2] * s0 + acc[b][nt][3] * s1;
            dsum[0] += acc[b][nt][0] * d0 + acc[b][nt][1] * d1;
            dsum[1] += acc[b][nt][2] * d0 + acc[b][nt][3] * d1;
        }
#pragma unroll
        for (int d = 1; d <= 2; d <<= 1)
#pragma unroll
            for (int rr = 0; rr < 2; rr++) {
                ssum[rr] += __shfl_xor_sync(0xFFFFFFFF, ssum[rr], d);
                dsum[rr] += __shfl_xor_sync(0xFFFFFFFF, dsum[rr], d);
            }
        if (lt == 0) {
            if (m0 < NN) {
                g_ssrc[b][m0 * 4 + h] = ssum[0];
                g_sdst[b][m0 * 4 + h] = dsum[0];
            }
            if (m1 < NN) {
                g_ssrc[b][m1 * 4 + h] = ssum[1];
                g_sdst[b][m1 * 4 + h] = dsum[1];
            }
        }
    }
}

// ---------------- deg: pure in-degree histogram ----------------
__global__ void deg_kernel(const int* __restrict__ t0, const int* __restrict__ t1)
{
    int idx = blockIdx.x * blockDim.x + threadIdx.x;
    if (idx >= 2 * EE) return;
    const int branch = (idx >= EE) ? 1 : 0;
    const int e = idx - branch * EE;
    const int tgt = (branch ? t1 : t0)[e];
    atomicAdd(&g_deg[branch * NN + tgt], 1);
}

// ---------------- alloc: warp-aggregated order-free CSR segment allocation ----------------
__global__ void alloc_kernel() {
    const int i = blockIdx.x * blockDim.x + threadIdx.x;
    if (i >= 2 * NN) return;
    const int lane = threadIdx.x & 31;
    const int deg = g_deg[i];
    int incl = deg;
#pragma unroll
    for (int d = 1; d < 32; d <<= 1) {
        int v = __shfl_up_sync(0xFFFFFFFF, incl, d);
        if (lane >= d) incl += v;
    }
    const int excl = incl - deg;
    int base = 0;
    if (lane == 31) base = atomicAdd(&g_total, incl);
    base = __shfl_sync(0xFFFFFFFF, base, 31);
    g_off[i] = base + excl;
    g_cur[i] = base + excl;
}

// ---------------- scatter: src indices into target-sorted order ----------------
__global__ void scatter_kernel(const int* __restrict__ t0, const int* __restrict__ s0,
                               const int* __restrict__ t1, const int* __restrict__ s1)
{
    int idx = blockIdx.x * blockDim.x + threadIdx.x;
    if (idx >= 2 * EE) return;
    const int branch = (idx >= EE) ? 1 : 0;
    const int e = idx - branch * EE;
    const int tgt = (branch ? t1 : t0)[e];
    const int src = (branch ? s1 : s0)[e];
    int pos = atomicAdd(&g_cur[branch * NN + tgt], 1);
    g_psrc[pos] = src;
}

// ---------------- agg: warp per node; fp16 gathers; inline softmax; single write ----------------
__global__ __launch_bounds__(256) void agg_kernel(float* __restrict__ out)
{
    const int gw = (blockIdx.x * blockDim.x + threadIdx.x) >> 5;
    if (gw >= NN) return;
    const int n = gw;
    const int lane = threadIdx.x & 31;
    const int h = lane >> 3;

    float4 acc = make_float4(0.f, 0.f, 0.f, 0.f);
#pragma unroll
    for (int b = 0; b < 2; b++) {
        const int base_i = b * NN + n;
        const int off = g_off[base_i];
        const int deg = g_deg[base_i];
        const float sdh = g_sdst[b][n * 4 + h];
        const __half* __restrict__ xm = g_xm[b];
        const float* __restrict__ ssrc = g_ssrc[b];

        float4 accb = make_float4(0.f, 0.f, 0.f, 0.f);
        float sumw = 0.f;
        for (int bs = 0; bs < deg; bs += 32) {
            const int cnt = min(deg - bs, 32);
            const int my = (lane < cnt) ? g_psrc[off + bs + lane] : 0;
#pragma unroll 4
            for (int j = 0; j < cnt; j++) {
                const int s = __shfl_sync(0xFFFFFFFF, my, j);
                const float ssh = __ldg(&ssrc[s * 4 + h]);
                const __half2* hp = (const __half2*)&xm[s * 128 + lane * 4];
                const float2 v01 = __half22float2(hp[0]);
                const float2 v23 = __half22float2(hp[1]);
                const float w = lrelu_exp(ssh + sdh);
                sumw += w;
                accb.x += w * v01.x;
                accb.y += w * v01.y;
                accb.z += w * v23.x;
                accb.w += w * v23.y;
            }
        }
        const float inv = __frcp_rn(sumw + 1e-16f);
        acc.x += accb.x * inv;
        acc.y += accb.y * inv;
        acc.z += accb.z * inv;
        acc.w += accb.w * inv;
    }
    float4* po = (float4*)&out[n * 128 + lane * 4];
    float4 o = *po;   // skip*EPS already written by gemm
    o.x = fmaxf(o.x + acc.x, 0.f);
    o.y = fmaxf(o.y + acc.y, 0.f);
    o.z = fmaxf(o.z + acc.z, 0.f);
    o.w = fmaxf(o.w + acc.w, 0.f);
    *po = o;
}

// ---------------- launch ----------------
extern "C" void kernel_launch(void* const* d_in, const int* in_sizes, int n_in,
                              void* d_out, int out_size)
{
    const float* x      = (const float*)d_in[0];
    const float* W_low  = (const float*)d_in[1];
    const float* a_sl   = (const float*)d_in[2];
    const float* a_dl   = (const float*)d_in[3];
    const float* W_up   = (const float*)d_in[4];
    const float* a_su   = (const float*)d_in[5];
    const float* a_du   = (const float*)d_in[6];
    const float* W_skip = (const float*)d_in[7];
    const int* lower_tgt = (const int*)d_in[8];
    const int* lower_src = (const int*)d_in[9];
    const int* upper_tgt = (const int*)d_in[10];
    const int* upper_src = (const int*)d_in[11];
    float* out = (float*)d_out;

    static cudaStream_t s2 = nullptr;
    static cudaEvent_t e_fork = nullptr, e_join = nullptr;
    if (!s2) {
        cudaFuncSetAttribute(gemm_mma_kernel,
                             cudaFuncAttributeMaxDynamicSharedMemorySize, GEMM_SMEM);
        cudaStreamCreateWithFlags(&s2, cudaStreamNonBlocking);
        cudaEventCreateWithFlags(&e_fork, cudaEventDisableTiming);
        cudaEventCreateWithFlags(&e_join, cudaEventDisableTiming);
    }

    // fork: CSR chain on side stream, GEMM chain on main stream
    cudaEventRecord(e_fork, 0);
    cudaStreamWaitEvent(s2, e_fork, 0);

    // side stream: zero -> deg -> alloc -> scatter
    zero_kernel<<<(2 * NN + 255) / 256, 256, 0, s2>>>();
    deg_kernel<<<(2 * EE + 255) / 256, 256, 0, s2>>>(lower_tgt, upper_tgt);
    alloc_kernel<<<(2 * NN + 255) / 256, 256, 0, s2>>>();
    scatter_kernel<<<(2 * EE + 255) / 256, 256, 0, s2>>>(lower_tgt, lower_src,
                                                         upper_tgt, upper_src);
    cudaEventRecord(e_join, s2);

    // main stream: prep -> gemm (fused 3-branch, N-quarter, K-chunked)
    prep_b_kernel<<<(3 * 8192 + 255) / 256, 256>>>(W_low, W_up, W_skip);
    dim3 ggrid((NN + 127) / 128, 4);
    gemm_mma_kernel<<<ggrid, 256, GEMM_SMEM>>>(x, out, a_sl, a_dl, a_su, a_du);

    // join: agg needs gemm (main) + scatter (side)
    cudaStreamWaitEvent(0, e_join, 0);
    {
        long long threads = (long long)NN * 32;
        int blocks = (int)((threads + 255) / 256);
        agg_kernel<<<blocks, 256>>>(out);
    }
}

// round 16
// speedup vs baseline: 1.0767x; 1.0129x over previous
#include <cuda_runtime.h>
#include <cuda_bf16.h>
#include <cuda_fp16.h>
#include <cstdint>

#define NN 50000
#define EE 400000
#define EPS_SKIP_F 1.000001f

// ---------------- scratch ----------------
__device__ __half   g_xm[2][NN * 128];   // per-branch transformed features (fp16)
__device__ float    g_ssrc[2][NN * 4];
__device__ float    g_sdst[2][NN * 4];
__device__ int      g_deg[2 * NN];
__device__ int      g_off[2 * NN];
__device__ int      g_cur[2 * NN];
__device__ int      g_psrc[2 * EE];      // target-sorted source indices
__device__ int      g_total;             // global segment cursor
__device__ uint32_t g_Wtp[3][2][128 * 64];  // W^T split: [branch][hi/lo][n][kpair] bf16x2

// ---------------- helpers ----------------
__device__ __forceinline__ void split_pack(float v0, float v1, uint32_t& hi, uint32_t& lo) {
    __nv_bfloat16 h0 = __float2bfloat16_rn(v0);
    __nv_bfloat16 h1 = __float2bfloat16_rn(v1);
    float r0 = v0 - __bfloat162float(h0);
    float r1 = v1 - __bfloat162float(h1);
    __nv_bfloat162 hp; hp.x = h0; hp.y = h1;
    __nv_bfloat162 lp; lp.x = __float2bfloat16_rn(r0); lp.y = __float2bfloat16_rn(r1);
    hi = *(uint32_t*)&hp;
    lo = *(uint32_t*)&lp;
}

__device__ __forceinline__ void mma_bf16(float* d,
                                         uint32_t a0, uint32_t a1, uint32_t a2, uint32_t a3,
                                         uint32_t b0, uint32_t b1) {
    asm volatile(
        "mma.sync.aligned.m16n8k16.row.col.f32.bf16.bf16.f32 "
        "{%0,%1,%2,%3}, {%4,%5,%6,%7}, {%8,%9}, {%0,%1,%2,%3};"
        : "+f"(d[0]), "+f"(d[1]), "+f"(d[2]), "+f"(d[3])
        : "r"(a0), "r"(a1), "r"(a2), "r"(a3), "r"(b0), "r"(b1));
}

__device__ __forceinline__ float lrelu_exp(float a) {
    a = (a > 0.f) ? a : 0.01f * a;
    return __expf(a);
}

// ---------------- zero (side stream): deg + cursor ----------------
__global__ void zero_kernel() {
    int i = blockIdx.x * blockDim.x + threadIdx.x;
    if (i == 0) g_total = 0;
    if (i < 2 * NN) g_deg[i] = 0;
}

// ---------------- prep: W split/transpose only ----------------
__global__ void prep_b_kernel(const float* __restrict__ Wl,
                              const float* __restrict__ Wu,
                              const float* __restrict__ Ws) {
    int i = blockIdx.x * blockDim.x + threadIdx.x;
    if (i >= 3 * 8192) return;
    const int b = i / 8192;
    const int r = i & 8191;
    const int n = r >> 6, kp = r & 63;
    const float* __restrict__ W = (b == 0) ? Wl : ((b == 1) ? Wu : Ws);
    const float v0 = W[(2 * kp) * 128 + n];
    const float v1 = W[(2 * kp + 1) * 128 + n];
    uint32_t hi, lo;
    split_pack(v0, v1, hi, lo);
    g_Wtp[b][0][n * 64 + kp] = hi;
    g_Wtp[b][1][n * 64 + kp] = lo;
}

// ---------------- fused 3-branch GEMM: N-quarter, K-chunked, A reg-prefetch pipeline ----------------
#define PADC 36
#define ACSZ (128 * PADC)
#define BCSZ (32 * PADC)
#define GEMM_SMEM ((2 * ACSZ + 6 * BCSZ) * 4)   // 64,512 B

__global__ __launch_bounds__(256, 2) void gemm_mma_kernel(
    const float* __restrict__ x, float* __restrict__ out_skip,
    const float* __restrict__ a_sl, const float* __restrict__ a_dl,
    const float* __restrict__ a_su, const float* __restrict__ a_du)
{
    extern __shared__ uint32_t smem[];
    uint32_t* Ah = smem;
    uint32_t* Al = smem + ACSZ;
    uint32_t* Bbase = smem + 2 * ACSZ;   // [(b*2+hl)][BCSZ]

    const int nq = blockIdx.y;           // N-quarter: cols [nq*32, nq*32+32) = head nq
    const int bm0 = blockIdx.x * 128;

    const int t = threadIdx.x;
    const int wid = t >> 5, lane = t & 31;
    const int lg = lane >> 2;
    const int lt = lane & 3;
    const int wm = wid * 16;

    float acc[3][4][4];
#pragma unroll
    for (int b = 0; b < 3; b++)
#pragma unroll
        for (int nt = 0; nt < 4; nt++)
#pragma unroll
            for (int c = 0; c < 4; c++) acc[b][nt][c] = 0.f;

    // ---- load chunk 0: A (split) + B (all 3 branches) ----
#pragma unroll
    for (int i = t; i < 2048; i += 256) {
        const int row = i >> 4;
        const int c4 = i & 15;
        const int m = bm0 + row;
        float4 v = make_float4(0.f, 0.f, 0.f, 0.f);
        if (m < NN) v = *(const float4*)&x[m * 128 + c4 * 4];
        uint32_t h0, l0, h1, l1;
        split_pack(v.x, v.y, h0, l0);
        split_pack(v.z, v.w, h1, l1);
        const int base = row * PADC + 2 * c4;
        Ah[base] = h0; Ah[base + 1] = h1;
        Al[base] = l0; Al[base + 1] = l1;
    }
#pragma unroll
    for (int i = t; i < 3 * 256; i += 256) {
        const int b = i >> 8;
        const int r = i & 255;
        const int n = r >> 3;
        const int p4 = r & 7;
        const int gn = nq * 32 + n;
        uint4 vh = *(const uint4*)&g_Wtp[b][0][gn * 64 + p4 * 4];
        uint4 vl = *(const uint4*)&g_Wtp[b][1][gn * 64 + p4 * 4];
        *(uint4*)&Bbase[(b * 2 + 0) * BCSZ + n * PADC + p4 * 4] = vh;
        *(uint4*)&Bbase[(b * 2 + 1) * BCSZ + n * PADC + p4 * 4] = vl;
    }
    __syncthreads();

    // ---- prefetch chunk 1's A into registers (hides LDG behind chunk-0 compute) ----
    float4 a_pf[8];
#pragma unroll
    for (int i = 0; i < 8; i++) {
        const int idx = t + i * 256;
        const int row = idx >> 4;
        const int c4 = idx & 15;
        const int m = bm0 + row;
        a_pf[i] = make_float4(0.f, 0.f, 0.f, 0.f);
        if (m < NN) a_pf[i] = *(const float4*)&x[m * 128 + (16 + c4) * 4];
    }

#pragma unroll
    for (int ch = 0; ch < 2; ch++) {
        // ---- compute 4 k16-steps over this chunk ----
#pragma unroll
        for (int ks = 0; ks < 4; ks++) {
            const int kp = ks * 8;
            const int rb = wm + lg;
            const int i0 = rb * PADC + kp + lt;
            const int i1 = (rb + 8) * PADC + kp + lt;
            uint32_t ah[4], al[4];
            ah[0] = Ah[i0];     al[0] = Al[i0];
            ah[1] = Ah[i1];     al[1] = Al[i1];
            ah[2] = Ah[i0 + 4]; al[2] = Al[i0 + 4];
            ah[3] = Ah[i1 + 4]; al[3] = Al[i1 + 4];
#pragma unroll
            for (int b = 0; b < 3; b++) {
                const uint32_t* Bh = Bbase + (b * 2 + 0) * BCSZ;
                const uint32_t* Bl = Bbase + (b * 2 + 1) * BCSZ;
#pragma unroll
                for (int nt = 0; nt < 4; nt++) {
                    const int n = nt * 8 + lg;
                    const int bi = n * PADC + kp + lt;
                    const uint32_t bh0 = Bh[bi], bh1 = Bh[bi + 4];
                    const uint32_t bl0 = Bl[bi], bl1 = Bl[bi + 4];
                    mma_bf16(acc[b][nt], ah[0], ah[1], ah[2], ah[3], bl0, bl1);
                    mma_bf16(acc[b][nt], al[0], al[1], al[2], al[3], bh0, bh1);
                    mma_bf16(acc[b][nt], ah[0], ah[1], ah[2], ah[3], bh0, bh1);
                }
            }
        }

        if (ch == 0) {
            // ---- stage chunk 1: split prefetched A into smem; load small B chunk ----
            __syncthreads();   // chunk-0 reads done before overwrite
#pragma unroll
            for (int i = 0; i < 8; i++) {
                const int idx = t + i * 256;
                const int row = idx >> 4;
                const int c4 = idx & 15;
                uint32_t h0, l0, h1, l1;
                split_pack(a_pf[i].x, a_pf[i].y, h0, l0);
                split_pack(a_pf[i].z, a_pf[i].w, h1, l1);
                const int base = row * PADC + 2 * c4;
                Ah[base] = h0; Ah[base + 1] = h1;
                Al[base] = l0; Al[base + 1] = l1;
            }
#pragma unroll
            for (int i = t; i < 3 * 256; i += 256) {
                const int b = i >> 8;
                const int r = i & 255;
                const int n = r >> 3;
                const int p4 = r & 7;
                const int gn = nq * 32 + n;
                uint4 vh = *(const uint4*)&g_Wtp[b][0][gn * 64 + 32 + p4 * 4];
                uint4 vl = *(const uint4*)&g_Wtp[b][1][gn * 64 + 32 + p4 * 4];
                *(uint4*)&Bbase[(b * 2 + 0) * BCSZ + n * PADC + p4 * 4] = vh;
                *(uint4*)&Bbase[(b * 2 + 1) * BCSZ + n * PADC + p4 * 4] = vl;
            }
            __syncthreads();
        }
    }

    // ---- epilogue ----
    const int m0 = bm0 + wm + lg;
    const int m1 = m0 + 8;
#pragma unroll
    for (int b = 0; b < 2; b++) {
        __half* __restrict__ out = g_xm[b];
#pragma unroll
        for (int nt = 0; nt < 4; nt++) {
            const int col = nq * 32 + nt * 8 + 2 * lt;
            if (m0 < NN) {
                __half2 v = __floats2half2_rn(acc[b][nt][0], acc[b][nt][1]);
                *(__half2*)&out[m0 * 128 + col] = v;
            }
            if (m1 < NN) {
                __half2 v = __floats2half2_rn(acc[b][nt][2], acc[b][nt][3]);
                *(__half2*)&out[m1 * 128 + col] = v;
            }
        }
    }
#pragma unroll
    for (int nt = 0; nt < 4; nt++) {
        const int col = nq * 32 + nt * 8 + 2 * lt;
        if (m0 < NN) {
            float2 v = make_float2(acc[2][nt][0] * EPS_SKIP_F, acc[2][nt][1] * EPS_SKIP_F);
            *(float2*)&out_skip[m0 * 128 + col] = v;
        }
        if (m1 < NN) {
            float2 v = make_float2(acc[2][nt][2] * EPS_SKIP_F, acc[2][nt][3] * EPS_SKIP_F);
            *(float2*)&out_skip[m1 * 128 + col] = v;
        }
    }

    // ---- fused logit epilogue: this warp owns head nq for its 16 rows ----
    const int h = nq;
#pragma unroll
    for (int b = 0; b < 2; b++) {
        const float* __restrict__ asrc = (b == 0) ? a_sl : a_su;
        const float* __restrict__ adst = (b == 0) ? a_dl : a_du;
        float ssum[2] = {0.f, 0.f};
        float dsum[2] = {0.f, 0.f};
#pragma unroll
        for (int nt = 0; nt < 4; nt++) {
            const int ai = h * 32 + nt * 8 + 2 * lt;
            const float s0 = asrc[ai], s1 = asrc[ai + 1];
            const float d0 = adst[ai], d1 = adst[ai + 1];
            ssum[0] += acc[b][nt][0] * s0 + acc[b][nt][1] * s1;
            ssum[1] += acc[b][nt][2] * s0 + acc[b][nt][3] * s1;
            dsum[0] += acc[b][nt][0] * d0 + acc[b][nt][1] * d1;
            dsum[1] += acc[b][nt][2] * d0 + acc[b][nt][3] * d1;
        }
#pragma unroll
        for (int d = 1; d <= 2; d <<= 1)
#pragma unroll
            for (int rr = 0; rr < 2; rr++) {
                ssum[rr] += __shfl_xor_sync(0xFFFFFFFF, ssum[rr], d);
                dsum[rr] += __shfl_xor_sync(0xFFFFFFFF, dsum[rr], d);
            }
        if (lt == 0) {
            if (m0 < NN) {
                g_ssrc[b][m0 * 4 + h] = ssum[0];
                g_sdst[b][m0 * 4 + h] = dsum[0];
            }
            if (m1 < NN) {
                g_ssrc[b][m1 * 4 + h] = ssum[1];
                g_sdst[b][m1 * 4 + h] = dsum[1];
            }
        }
    }
}

// ---------------- deg: pure in-degree histogram ----------------
__global__ void deg_kernel(const int* __restrict__ t0, const int* __restrict__ t1)
{
    int idx = blockIdx.x * blockDim.x + threadIdx.x;
    if (idx >= 2 * EE) return;
    const int branch = (idx >= EE) ? 1 : 0;
    const int e = idx - branch * EE;
    const int tgt = (branch ? t1 : t0)[e];
    atomicAdd(&g_deg[branch * NN + tgt], 1);
}

// ---------------- alloc: warp-aggregated order-free CSR segment allocation ----------------
__global__ void alloc_kernel() {
    const int i = blockIdx.x * blockDim.x + threadIdx.x;
    if (i >= 2 * NN) return;
    const int lane = threadIdx.x & 31;
    const int deg = g_deg[i];
    int incl = deg;
#pragma unroll
    for (int d = 1; d < 32; d <<= 1) {
        int v = __shfl_up_sync(0xFFFFFFFF, incl, d);
        if (lane >= d) incl += v;
    }
    const int excl = incl - deg;
    int base = 0;
    if (lane == 31) base = atomicAdd(&g_total, incl);
    base = __shfl_sync(0xFFFFFFFF, base, 31);
    g_off[i] = base + excl;
    g_cur[i] = base + excl;
}

// ---------------- scatter: src indices into target-sorted order ----------------
__global__ void scatter_kernel(const int* __restrict__ t0, const int* __restrict__ s0,
                               const int* __restrict__ t1, const int* __restrict__ s1)
{
    int idx = blockIdx.x * blockDim.x + threadIdx.x;
    if (idx >= 2 * EE) return;
    const int branch = (idx >= EE) ? 1 : 0;
    const int e = idx - branch * EE;
    const int tgt = (branch ? t1 : t0)[e];
    const int src = (branch ? s1 : s0)[e];
    int pos = atomicAdd(&g_cur[branch * NN + tgt], 1);
    g_psrc[pos] = src;
}

// ---------------- agg: warp per node; fp16 gathers; inline softmax; single write ----------------
__global__ __launch_bounds__(256) void agg_kernel(float* __restrict__ out)
{
    const int gw = (blockIdx.x * blockDim.x + threadIdx.x) >> 5;
    if (gw >= NN) return;
    const int n = gw;
    const int lane = threadIdx.x & 31;
    const int h = lane >> 3;

    float4 acc = make_float4(0.f, 0.f, 0.f, 0.f);
#pragma unroll
    for (int b = 0; b < 2; b++) {
        const int base_i = b * NN + n;
        const int off = g_off[base_i];
        const int deg = g_deg[base_i];
        const float sdh = g_sdst[b][n * 4 + h];
        const __half* __restrict__ xm = g_xm[b];
        const float* __restrict__ ssrc = g_ssrc[b];

        float4 accb = make_float4(0.f, 0.f, 0.f, 0.f);
        float sumw = 0.f;
        for (int bs = 0; bs < deg; bs += 32) {
            const int cnt = min(deg - bs, 32);
            const int my = (lane < cnt) ? g_psrc[off + bs + lane] : 0;
#pragma unroll 4
            for (int j = 0; j < cnt; j++) {
                const int s = __shfl_sync(0xFFFFFFFF, my, j);
                const float ssh = __ldg(&ssrc[s * 4 + h]);
                const __half2* hp = (const __half2*)&xm[s * 128 + lane * 4];
                const float2 v01 = __half22float2(hp[0]);
                const float2 v23 = __half22float2(hp[1]);
                const float w = lrelu_exp(ssh + sdh);
                sumw += w;
                accb.x += w * v01.x;
                accb.y += w * v01.y;
                accb.z += w * v23.x;
                accb.w += w * v23.y;
            }
        }
        const float inv = __frcp_rn(sumw + 1e-16f);
        acc.x += accb.x * inv;
        acc.y += accb.y * inv;
        acc.z += accb.z * inv;
        acc.w += accb.w * inv;
    }
    float4* po = (float4*)&out[n * 128 + lane * 4];
    float4 o = *po;   // skip*EPS already written by gemm
    o.x = fmaxf(o.x + acc.x, 0.f);
    o.y = fmaxf(o.y + acc.y, 0.f);
    o.z = fmaxf(o.z + acc.z, 0.f);
    o.w = fmaxf(o.w + acc.w, 0.f);
    *po = o;
}

// ---------------- launch ----------------
extern "C" void kernel_launch(void* const* d_in, const int* in_sizes, int n_in,
                              void* d_out, int out_size)
{
    const float* x      = (const float*)d_in[0];
    const float* W_low  = (const float*)d_in[1];
    const float* a_sl   = (const float*)d_in[2];
    const float* a_dl   = (const float*)d_in[3];
    const float* W_up   = (const float*)d_in[4];
    const float* a_su   = (const float*)d_in[5];
    const float* a_du   = (const float*)d_in[6];
    const float* W_skip = (const float*)d_in[7];
    const int* lower_tgt = (const int*)d_in[8];
    const int* lower_src = (const int*)d_in[9];
    const int* upper_tgt = (const int*)d_in[10];
    const int* upper_src = (const int*)d_in[11];
    float* out = (float*)d_out;

    static cudaStream_t s2 = nullptr;
    static cudaEvent_t e_fork = nullptr, e_join = nullptr;
    if (!s2) {
        cudaFuncSetAttribute(gemm_mma_kernel,
                             cudaFuncAttributeMaxDynamicSharedMemorySize, GEMM_SMEM);
        cudaStreamCreateWithFlags(&s2, cudaStreamNonBlocking);
        cudaEventCreateWithFlags(&e_fork, cudaEventDisableTiming);
        cudaEventCreateWithFlags(&e_join, cudaEventDisableTiming);
    }

    // fork: CSR chain on side stream, GEMM chain on main stream
    cudaEventRecord(e_fork, 0);
    cudaStreamWaitEvent(s2, e_fork, 0);

    // side stream: zero -> deg -> alloc -> scatter
    zero_kernel<<<(2 * NN + 255) / 256, 256, 0, s2>>>();
    deg_kernel<<<(2 * EE + 255) / 256, 256, 0, s2>>>(lower_tgt, upper_tgt);
    alloc_kernel<<<(2 * NN + 255) / 256, 256, 0, s2>>>();
    scatter_kernel<<<(2 * EE + 255) / 256, 256, 0, s2>>>(lower_tgt, lower_src,
                                                         upper_tgt, upper_src);
    cudaEventRecord(e_join, s2);

    // main stream: prep -> gemm (pipelined)
    prep_b_kernel<<<(3 * 8192 + 255) / 256, 256>>>(W_low, W_up, W_skip);
    dim3 ggrid((NN + 127) / 128, 4);
    gemm_mma_kernel<<<ggrid, 256, GEMM_SMEM>>>(x, out, a_sl, a_dl, a_su, a_du);

    // join: agg needs gemm (main) + scatter (side)
    cudaStreamWaitEvent(0, e_join, 0);
    {
        long long threads = (long long)NN * 32;
        int blocks = (int)((threads + 255) / 256);
        agg_kernel<<<blocks, 256>>>(out);
    }
}